// round 17
// baseline (speedup 1.0000x reference)
#include <cuda_runtime.h>

#define BB 256      // batch
#define NN 2048     // nodes
#define UU 128      // node_units
#define GG 256      // graph_units
#define NC4 (NN/4)  // 512 float4 columns
#define PR  256     // partial rows (8 adj rows each)
#define NPREP 4     // prep blocks (32 u each)
#define NCOLB 512                   // colsum blocks (bid 0..511)
#define PREP0 NCOLB                 // prep blocks   (bid 512..515)
#define OUT0  (NCOLB + NPREP)       // output blocks (bid 516..771)
#define NGRID (OUT0 + BB)           // 772 total

// Device globals. g_part/g_c/g_ApP/g_AmP fully rewritten every launch;
// only the three counters carry state (reset by the last output block).
__device__ float g_part[PR * NN];    // partial column sums (2 MB, disjoint)
__device__ float g_c[NN];            // full column sums
__device__ float g_ApP[NPREP][GG];   // partial sum_{u:w1>0} w1[u]*w2[u,g]
__device__ float g_AmP[NPREP][GG];   // partial sum_{u:w1<0} w1[u]*w2[u,g]
__device__ int   g_b1nz;             // 1 iff any b1[u] != 0
__device__ int   g_ctr1;             // colsum+prep arrivals (target 516)
__device__ int   g_ctr2;             // reducer arrivals     (target 8)
__device__ int   g_ctr3;             // output exits -> counter reset

// ---------------------------------------------------------------------------
// One kernel, three roles, streamers first in bid order (liveness guarantee:
// earlier blocks never wait on later ones; queued blocks only ever wait on
// blocks with smaller bids).
// ---------------------------------------------------------------------------
__global__ void __launch_bounds__(256, 5)
mono(const float4* __restrict__ nf4,
     const float4* __restrict__ adj4,
     const float*  __restrict__ w1,
     const float*  __restrict__ b1,
     const float*  __restrict__ w2,
     const float*  __restrict__ b2,
     float*        __restrict__ out) {
    const int bid = blockIdx.x;
    const int tid = threadIdx.x;

    if (bid < NCOLB) {
        // ---- Role A: colsum partials (proven k1 shape: 8 rows x half-cols)
        const int c4 = (bid & 1) * 256 + tid;   // f4 column 0..511
        const int pr = bid >> 1;                // partial row 0..255
        const int r0 = pr * 8;
        float4 a[8];
#pragma unroll
        for (int r = 0; r < 8; r++)
            a[r] = adj4[(size_t)(r0 + r) * NC4 + c4];
        float4 s = a[0];
#pragma unroll
        for (int r = 1; r < 8; r++) {
            s.x += a[r].x; s.y += a[r].y; s.z += a[r].z; s.w += a[r].w;
        }
        ((float4*)g_part)[(size_t)pr * NC4 + c4] = s;

        __threadfence();
        __syncthreads();
        if (tid == 0) atomicAdd(&g_ctr1, 1);
        return;
    }

    if (bid < OUT0) {
        // ---- Role B: fold a 32-u slice of w1 through w2 (+ b1 flag)
        const int k  = bid - PREP0;
        const int u0 = k * 32;
        float ap = 0.f, am = 0.f;
#pragma unroll 8
        for (int u = 0; u < 32; u++) {
            const float w = w1[u0 + u];
            const float x = w2[(u0 + u) * GG + tid];
            if (w > 0.f) ap = fmaf(w, x, ap);
            else         am = fmaf(w, x, am);
        }
        g_ApP[k][tid] = ap;
        g_AmP[k][tid] = am;
        if (k == 0) {
            int nz = (tid < UU && b1[tid] != 0.f) ? 1 : 0;
            nz = __syncthreads_or(nz);
            if (tid == 0) g_b1nz = nz;
        }
        __threadfence();
        __syncthreads();
        if (tid == 0) atomicAdd(&g_ctr1, 1);
        return;
    }

    // ---- Role C: output block for batch b. Prefetch nf FIRST (overlaps
    // with the adj stream since these blocks are co-resident with Role A).
    const int b = bid - OUT0;
    const float4 v0 = nf4[(size_t)b * NC4 + tid];
    const float4 v1 = nf4[(size_t)b * NC4 + 256 + tid];

    if (b < 8) {
        // First 8 output blocks double as reducers.
        if (tid == 0) {
            while (*(volatile int*)&g_ctr1 < NCOLB + NPREP) { __nanosleep(32); }
        }
        __syncthreads();
        __threadfence();
        const int j = b * 256 + tid;            // column 0..2047
        float s = 0.f;
#pragma unroll 16
        for (int y = 0; y < PR; y++) s += g_part[(size_t)y * NN + j];
        g_c[j] = s;                             // raw sums; mean folded below
        __threadfence();
        __syncthreads();
        if (tid == 0) atomicAdd(&g_ctr2, 1);
    }

    // All output blocks wait for the full g_c (+ prep, implied by ctr1 leg).
    if (tid == 0) {
        while (*(volatile int*)&g_ctr2 < 8) { __nanosleep(32); }
    }
    __syncthreads();
    __threadfence();

    // ---- compute P/M from prefetched nf + L2-hot g_c
    const float4 c0 = ((const float4*)g_c)[tid];
    const float4 c1 = ((const float4*)g_c)[256 + tid];
    float p = 0.f, m = 0.f;
    p = fmaf(c0.x, fmaxf(v0.x, 0.f), p);  m = fmaf(c0.x, fminf(v0.x, 0.f), m);
    p = fmaf(c0.y, fmaxf(v0.y, 0.f), p);  m = fmaf(c0.y, fminf(v0.y, 0.f), m);
    p = fmaf(c0.z, fmaxf(v0.z, 0.f), p);  m = fmaf(c0.z, fminf(v0.z, 0.f), m);
    p = fmaf(c0.w, fmaxf(v0.w, 0.f), p);  m = fmaf(c0.w, fminf(v0.w, 0.f), m);
    p = fmaf(c1.x, fmaxf(v1.x, 0.f), p);  m = fmaf(c1.x, fminf(v1.x, 0.f), m);
    p = fmaf(c1.y, fmaxf(v1.y, 0.f), p);  m = fmaf(c1.y, fminf(v1.y, 0.f), m);
    p = fmaf(c1.z, fmaxf(v1.z, 0.f), p);  m = fmaf(c1.z, fminf(v1.z, 0.f), m);
    p = fmaf(c1.w, fmaxf(v1.w, 0.f), p);  m = fmaf(c1.w, fminf(v1.w, 0.f), m);

#pragma unroll
    for (int o = 16; o > 0; o >>= 1) {
        p += __shfl_xor_sync(0xFFFFFFFFu, p, o);
        m += __shfl_xor_sync(0xFFFFFFFFu, m, o);
    }
    __shared__ float sp[8], sm_[8];
    const int w = tid >> 5;
    if ((tid & 31) == 0) { sp[w] = p; sm_[w] = m; }
    __syncthreads();
    float P = 0.f, M = 0.f;
#pragma unroll
    for (int i = 0; i < 8; i++) { P += sp[i]; M += sm_[i]; }
    P *= (1.0f / (float)NN);
    M *= (1.0f / (float)NN);

    if (!g_b1nz) {
        float ap = 0.f, am = 0.f;
#pragma unroll
        for (int k = 0; k < NPREP; k++) { ap += g_ApP[k][tid]; am += g_AmP[k][tid]; }
        const float o = fmaf(P, ap, fmaf(M, am, b2[tid]));
        out[(size_t)b * GG + tid] = fmaxf(o, 0.f);
    } else {
        // General path (b1 != 0): exact z[b,u] + small matmul. Never taken for
        // this dataset (b1 == 0); kept for correctness generality.
        __shared__ float zs[UU];
        if (tid < UU) {
            const float ww = w1[tid];
            const float bb = b1[tid];
            const float* row = (const float*)(nf4 + (size_t)b * NC4);
            float z = 0.f;
            for (int j = 0; j < NN; j++)
                z = fmaf(g_c[j] * (1.0f / (float)NN),
                         fmaxf(fmaf(row[j], ww, bb), 0.f), z);
            zs[tid] = z;
        }
        __syncthreads();
        float o = b2[tid];
#pragma unroll 4
        for (int u = 0; u < UU; u++) o = fmaf(zs[u], w2[u * GG + tid], o);
        out[(size_t)b * GG + tid] = fmaxf(o, 0.f);
    }

    // ---- last output block out resets the three counters for the next replay
    __syncthreads();
    if (tid == 0) {
        const int d = atomicAdd(&g_ctr3, 1);
        if (d == BB - 1) {
            g_ctr1 = 0; g_ctr2 = 0; g_ctr3 = 0;
            __threadfence();
        }
    }
}

// ---------------------------------------------------------------------------
extern "C" void kernel_launch(void* const* d_in, const int* in_sizes, int n_in,
                              void* d_out, int out_size) {
    const float* nf  = (const float*)d_in[0];   // (B, N)
    const float* adj = (const float*)d_in[1];   // (N, N)
    const float* w1  = (const float*)d_in[2];   // (1, U)
    const float* b1  = (const float*)d_in[3];   // (U,)
    const float* w2  = (const float*)d_in[4];   // (U, G)
    const float* b2  = (const float*)d_in[5];   // (G,)
    float* out = (float*)d_out;                 // (B, G)

    mono<<<NGRID, 256>>>((const float4*)nf, (const float4*)adj,
                         w1, b1, w2, b2, out);
}